// round 14
// baseline (speedup 1.0000x reference)
#include <cuda_runtime.h>
#include <cuda_bf16.h>
#include <cstdint>

#define T 256
#define Bt 64
#define EMB 300
#define HID 256
#define G4 1024
#define NLAB 20

typedef unsigned long long ull;

// ---------------- scratch ----------------
__device__ float g_xproj[2][T][G4][Bt];   // [dir][t][gate][batch]
__device__ float g_h[2][T][HID][Bt];      // [dir][t][hid][batch]
__device__ float g_em[T][Bt][NLAB];
__device__ float g_part[Bt];
__device__ __align__(16) unsigned g_flags[128];

// ---------------- f32x2 packed FMA (Blackwell) ----------------
__device__ __forceinline__ ull ffma2(ull a, ull b, ull c) {
    ull d;
    asm("fma.rn.f32x2 %0, %1, %2, %3;" : "=l"(d) : "l"(a), "l"(b), "l"(c));
    return d;
}
__device__ __forceinline__ float lo_hi_sum(ull v) {
    float2 f = *(float2*)&v;
    return f.x + f.y;
}

// ---------------- smem / async helpers ----------------
__device__ __forceinline__ uint32_t smem_u32(const void* p) {
    uint32_t a;
    asm("{ .reg .u64 t; cvta.to.shared.u64 t, %1; cvt.u32.u64 %0, t; }" : "=r"(a) : "l"(p));
    return a;
}
__device__ __forceinline__ void mbar_init(uint32_t mbar, uint32_t cnt) {
    asm volatile("mbarrier.init.shared.b64 [%0], %1;" :: "r"(mbar), "r"(cnt) : "memory");
}
__device__ __forceinline__ void mbar_expect_tx(uint32_t mbar, uint32_t bytes) {
    asm volatile("mbarrier.arrive.expect_tx.shared.b64 _, [%0], %1;" :: "r"(mbar), "r"(bytes) : "memory");
}
__device__ __forceinline__ void mbar_wait(uint32_t mbar, uint32_t phase) {
    asm volatile(
        "{\n\t.reg .pred P;\n"
        "WL_%=:\n\t"
        "mbarrier.try_wait.parity.shared.b64 P, [%0], %1;\n\t"
        "@!P bra WL_%=;\n\t}"
        :: "r"(mbar), "r"(phase) : "memory");
}
__device__ __forceinline__ void bulk_cp(uint32_t dst_smem, const void* src, uint32_t bytes, uint32_t mbar) {
    asm volatile(
        "cp.async.bulk.shared::cluster.global.mbarrier::complete_tx::bytes [%0], [%1], %2, [%3];"
        :: "r"(dst_smem), "l"(src), "r"(bytes), "r"(mbar) : "memory");
}
__device__ __forceinline__ void cp_async16(uint32_t dst, const void* src, uint32_t srcbytes) {
    asm volatile("cp.async.ca.shared.global [%0], [%1], 16, %2;"
                 :: "r"(dst), "l"(src), "r"(srcbytes) : "memory");
}
#define CP_COMMIT() asm volatile("cp.async.commit_group;" ::: "memory")
#define CP_WAIT1()  asm volatile("cp.async.wait_group 1;" ::: "memory")
#define CP_WAIT0()  asm volatile("cp.async.wait_group 0;" ::: "memory")
#define BAR_SYNC(id, cnt)   asm volatile("bar.sync %0, %1;"   :: "r"(id), "r"(cnt) : "memory")
#define BAR_ARRIVE(id, cnt) asm volatile("bar.arrive %0, %1;" :: "r"(id), "r"(cnt) : "memory")

// L2-served wide volatile load (NOT __ldcv: .cv bypasses L2 -> DRAM RTT).
__device__ __forceinline__ uint4 ld_vol4(const unsigned* p) {
    uint4 v;
    asm volatile("ld.volatile.global.v4.u32 {%0,%1,%2,%3}, [%4];"
                 : "=r"(v.x), "=r"(v.y), "=r"(v.z), "=r"(v.w) : "l"(p) : "memory");
    return v;
}

// =============================================================================
// Kernel 1: x_proj GEMM — R7 version (best measured): 64x64x32 tiles,
// 2-stage cp.async double buffer, f32x2 K-paired FMAs, 4x4 microtile.
// =============================================================================
__global__ void __launch_bounds__(256) k_xproj(
    const float* __restrict__ emb,
    const float* __restrict__ Wf, const float* __restrict__ bf,
    const float* __restrict__ Wb, const float* __restrict__ bb,
    const int*   __restrict__ sent)
{
    __shared__ float As[2][64 * 32];
    __shared__ float Bs[2][64 * 32];
    __shared__ int   ws[64];

    int t   = blockIdx.y;
    int n0  = blockIdx.x * 64;
    int dir = (n0 >= 1024) ? 1 : 0;
    const float* W    = dir ? Wb : Wf;
    const float* bias = dir ? bb : bf;
    int gbase = n0 & 1023;
    int tid = threadIdx.x;

    if (tid < 64) ws[tid] = sent[t * 64 + tid];
    __syncthreads();

    uint32_t as_base = smem_u32(&As[0][0]);
    uint32_t bs_base = smem_u32(&Bs[0][0]);

    int r0 = tid >> 3,          sl0 = tid & 7;
    int r1 = (tid + 256) >> 3,  sl1 = (tid + 256) & 7;
    uint32_t d0 = (uint32_t)(r0 * 128 + ((sl0 ^ (r0 & 7)) << 4));
    uint32_t d1 = (uint32_t)(r1 * 128 + ((sl1 ^ (r1 & 7)) << 4));
    const float* arow0 = emb + (size_t)ws[r0] * EMB;
    const float* arow1 = emb + (size_t)ws[r1] * EMB;
    const float* brow0 = W + (size_t)(gbase + r0) * EMB;
    const float* brow1 = W + (size_t)(gbase + r1) * EMB;

    auto issue = [&](int kt, int buf) {
        int k0 = kt * 32;
        uint32_t boff = (uint32_t)(buf * 8192);
        int kg0 = k0 + sl0 * 4, kg1 = k0 + sl1 * 4;
        uint32_t n0b = (kg0 + 4 <= EMB) ? 16u : 0u;
        uint32_t n1b = (kg1 + 4 <= EMB) ? 16u : 0u;
        cp_async16(as_base + boff + d0, arow0 + (n0b ? kg0 : 0), n0b);
        cp_async16(as_base + boff + d1, arow1 + (n1b ? kg1 : 0), n1b);
        cp_async16(bs_base + boff + d0, brow0 + (n0b ? kg0 : 0), n0b);
        cp_async16(bs_base + boff + d1, brow1 + (n1b ? kg1 : 0), n1b);
    };

    ull acc[4][4];
    #pragma unroll
    for (int i = 0; i < 4; i++)
        #pragma unroll
        for (int j = 0; j < 4; j++) acc[i][j] = 0ull;

    int tx = tid & 15;
    int ty = tid >> 4;
    int sa = tx & 7;
    int sb = ty & 7;

    issue(0, 0);
    CP_COMMIT();

    for (int kt = 0; kt < 10; kt++) {
        if (kt < 9) {
            issue(kt + 1, (kt + 1) & 1);
            CP_COMMIT();
            CP_WAIT1();
        } else {
            CP_WAIT0();
        }
        __syncthreads();

        const float* Ab = &As[kt & 1][0];
        const float* Bb = &Bs[kt & 1][0];
        #pragma unroll
        for (int c = 0; c < 8; c++) {
            ulonglong2 a[4], b[4];
            int ca = (c ^ sa) << 2;
            int cb = (c ^ sb) << 2;
            #pragma unroll
            for (int i = 0; i < 4; i++)
                a[i] = *(const ulonglong2*)&Ab[(tx + 16 * i) * 32 + ca];
            #pragma unroll
            for (int j = 0; j < 4; j++)
                b[j] = *(const ulonglong2*)&Bb[(ty + 16 * j) * 32 + cb];
            #pragma unroll
            for (int i = 0; i < 4; i++)
                #pragma unroll
                for (int j = 0; j < 4; j++) {
                    acc[i][j] = ffma2(a[i].x, b[j].x, acc[i][j]);
                    acc[i][j] = ffma2(a[i].y, b[j].y, acc[i][j]);
                }
        }
        __syncthreads();
    }

    #pragma unroll
    for (int j = 0; j < 4; j++) {
        int g = gbase + ty + 16 * j;
        float bv = bias[g];
        #pragma unroll
        for (int i = 0; i < 4; i++) {
            int m = tx + 16 * i;
            g_xproj[dir][t][g][m] = lo_hi_sum(acc[i][j]) + bv;
        }
    }
}

// =============================================================================
// Kernel 2: persistent bidirectional LSTM — warp-specialized sync.
// 288 threads: warps 0-7 compute (identical math to R13), warp 8 = sync warp:
//   bar2(288) <- hs free | 1-hop poll of all 128 flags (ld.volatile v4) |
//   issue 4 chunk TMAs.
// Compute warps: mbar_wait -> k-loop -> bar.arrive 2 -> red -> bar1(256) ->
//   act -> fence -> bar1 -> tid0 publishes flag.
// =============================================================================
__device__ __forceinline__ float sigf(float x) { return 1.f / (1.f + __expf(-x)); }

// smem: Ws2 32KB | hs 64KB | red 32KB | mbars
#define LSTM_SMEM (32768 + 65536 + 32768 + 64)

__global__ void __launch_bounds__(288) k_lstm(
    const float* __restrict__ Whf, const float* __restrict__ Whb)
{
    extern __shared__ float sm[];
    ull*   Ws2 = (ull*)sm;                  // [k=256][16 gates] dup-pairs, 32KB
    float* hs  = sm + 8192;                 // [k=256][b=64], 64KB
    float* red = sm + 8192 + 16384;         // [ks=8][gi=16][b=64], 32KB
    uint32_t mbar0 = smem_u32(sm + 32768);  // 4 mbarriers

    int bx  = blockIdx.x;
    int dir = bx >> 6;
    int cc  = bx & 63;
    const float* Whh = dir ? Whb : Whf;
    int tid = threadIdx.x;

    // replay-invariant base: flags are uniform at kernel entry.
    unsigned base0 = ((volatile unsigned*)g_flags)[bx];

    for (int idx = tid; idx < 4096; idx += 288) {
        int k = idx & 255, r = idx >> 8;
        int q = r >> 2, j = r & 3;
        float w = Whh[(q * 256 + 4 * cc + j) * HID + k];
        float2 w2 = make_float2(w, w);
        Ws2[k * 16 + r] = *(ull*)&w2;
    }
    if (tid == 0)
        for (int ch = 0; ch < 4; ch++) mbar_init(mbar0 + ch * 8, 1);
    __syncthreads();

    float* hb = &g_h[dir][0][0][0];
    uint32_t hs_smem = smem_u32(hs);

    if (tid < 256) {
        // ---------------- compute warps ----------------
        int lane = tid & 31;
        int ks   = tid >> 5;
        int gq   = lane >> 3;
        int bq   = lane & 7;
        int kbase = ks * 32;
        uint32_t my_mbar = mbar0 + (ks >> 1) * 8;

        int jrow = tid >> 6;
        int bcol = tid & 63;
        float cstate = 0.f;

        for (int step = 0; step < T; step++) {
            int t = dir ? (T - 1 - step) : step;

            float xp[4];
            #pragma unroll
            for (int q2 = 0; q2 < 4; q2++)
                xp[q2] = g_xproj[dir][t][q2 * 256 + 4 * cc + jrow][bcol];

            ull acc[4][4];
            #pragma unroll
            for (int j = 0; j < 4; j++)
                #pragma unroll
                for (int p = 0; p < 4; p++) acc[j][p] = 0ull;

            if (step > 0) {
                mbar_wait(my_mbar, (unsigned)(step - 1) & 1u);
                #pragma unroll 8
                for (int kk = 0; kk < 32; kk++) {
                    int k = kbase + kk;
                    const ull* wrow = Ws2 + k * 16 + gq * 4;
                    ulonglong2 wv0 = *(const ulonglong2*)wrow;
                    ulonglong2 wv1 = *(const ulonglong2*)(wrow + 2);
                    const float* hrow = hs + k * 64 + bq * 8;
                    ulonglong2 ha  = *(const ulonglong2*)hrow;
                    ulonglong2 hb2 = *(const ulonglong2*)(hrow + 4);
                    acc[0][0] = ffma2(wv0.x, ha.x,  acc[0][0]);
                    acc[0][1] = ffma2(wv0.x, ha.y,  acc[0][1]);
                    acc[0][2] = ffma2(wv0.x, hb2.x, acc[0][2]);
                    acc[0][3] = ffma2(wv0.x, hb2.y, acc[0][3]);
                    acc[1][0] = ffma2(wv0.y, ha.x,  acc[1][0]);
                    acc[1][1] = ffma2(wv0.y, ha.y,  acc[1][1]);
                    acc[1][2] = ffma2(wv0.y, hb2.x, acc[1][2]);
                    acc[1][3] = ffma2(wv0.y, hb2.y, acc[1][3]);
                    acc[2][0] = ffma2(wv1.x, ha.x,  acc[2][0]);
                    acc[2][1] = ffma2(wv1.x, ha.y,  acc[2][1]);
                    acc[2][2] = ffma2(wv1.x, hb2.x, acc[2][2]);
                    acc[2][3] = ffma2(wv1.x, hb2.y, acc[2][3]);
                    acc[3][0] = ffma2(wv1.y, ha.x,  acc[3][0]);
                    acc[3][1] = ffma2(wv1.y, ha.y,  acc[3][1]);
                    acc[3][2] = ffma2(wv1.y, hb2.x, acc[3][2]);
                    acc[3][3] = ffma2(wv1.y, hb2.y, acc[3][3]);
                }
            }

            // hs consumption done -> release sync warp for next TMA
            BAR_ARRIVE(2, 288);

            {
                float* rrow = red + (ks * 16 + gq * 4) * 64 + bq * 8;
                #pragma unroll
                for (int j = 0; j < 4; j++) {
                    ulonglong2 v0; v0.x = acc[j][0]; v0.y = acc[j][1];
                    ulonglong2 v1; v1.x = acc[j][2]; v1.y = acc[j][3];
                    *(ulonglong2*)(rrow + j * 64)     = v0;
                    *(ulonglong2*)(rrow + j * 64 + 4) = v1;
                }
            }
            BAR_SYNC(1, 256);

            float iv = xp[0], fv = xp[1], gv = xp[2], ov = xp[3];
            #pragma unroll
            for (int s = 0; s < 8; s++) {
                iv += red[(s * 16 +  0 + jrow) * 64 + bcol];
                fv += red[(s * 16 +  4 + jrow) * 64 + bcol];
                gv += red[(s * 16 +  8 + jrow) * 64 + bcol];
                ov += red[(s * 16 + 12 + jrow) * 64 + bcol];
            }
            cstate = sigf(fv) * cstate + sigf(iv) * tanhf(gv);
            float hv = sigf(ov) * tanhf(cstate);
            hb[t * HID * Bt + (4 * cc + jrow) * Bt + bcol] = hv;

            __threadfence();
            BAR_SYNC(1, 256);
            if (tid == 0)
                ((volatile unsigned*)g_flags)[bx] = base0 + (unsigned)(step + 1);
        }
    } else {
        // ---------------- sync warp (warp 8) ----------------
        int lane = tid & 31;
        const unsigned* fp = g_flags + lane * 4;   // 32 lanes x uint4 = 128 flags

        for (int s = 1; s < T; s++) {
            BAR_SYNC(2, 288);                      // hs free (step s-1 consumed)
            unsigned tgt = base0 + (unsigned)s;
            for (;;) {
                uint4 v = ld_vol4(fp);
                bool ok = (v.x >= tgt) & (v.y >= tgt) & (v.z >= tgt) & (v.w >= tgt);
                if (__all_sync(0xffffffffu, ok)) break;
            }
            if (lane == 0) {
                int t = dir ? (T - 1 - s) : s;
                int tprev = dir ? (t + 1) : (t - 1);
                const float* src = hb + tprev * HID * Bt;
                #pragma unroll
                for (int ch = 0; ch < 4; ch++) {
                    mbar_expect_tx(mbar0 + ch * 8, 16384);
                    bulk_cp(hs_smem + ch * 16384, src + ch * 4096, 16384, mbar0 + ch * 8);
                }
            }
        }
        BAR_SYNC(2, 288);                          // consume final arrivals
    }
}

// =============================================================================
// Kernel 3: emissions
// =============================================================================
__global__ void __launch_bounds__(256) k_emis(
    const float* __restrict__ Wt, const float* __restrict__ bt)
{
    extern __shared__ float sm[];
    float* Wts = sm;
    float* hch = sm + 10240;

    int t = blockIdx.x, tid = threadIdx.x;
    for (int i = tid; i < NLAB * 2 * HID; i += 256) Wts[i] = Wt[i];

    float acc[5] = {0.f, 0.f, 0.f, 0.f, 0.f};
    int b = tid & 63;
    int lbase = tid >> 6;

    for (int d = 0; d < 2; d++) {
        const float* hsrc = &g_h[d][t][0][0];
        for (int jc = 0; jc < 4; jc++) {
            __syncthreads();
            for (int i = tid; i < 4096; i += 256) hch[i] = hsrc[jc * 4096 + i];
            __syncthreads();
            #pragma unroll 4
            for (int j2 = 0; j2 < 64; j2++) {
                float hv = hch[j2 * 64 + b];
                #pragma unroll
                for (int s = 0; s < 5; s++) {
                    int l = lbase + 4 * s;
                    acc[s] += hv * Wts[l * 2 * HID + d * HID + jc * 64 + j2];
                }
            }
        }
    }
    #pragma unroll
    for (int s = 0; s < 5; s++) {
        int l = lbase + 4 * s;
        g_em[t][b][l] = acc[s] + bt[l];
    }
}

// =============================================================================
// Kernel 4: CRF per batch
// =============================================================================
__global__ void __launch_bounds__(64) k_crf(
    const int* __restrict__ sent, const int* __restrict__ labels,
    const float* __restrict__ start_t, const float* __restrict__ end_t,
    const float* __restrict__ trans)
{
    int b = blockIdx.x;
    int tid = threadIdx.x;
    __shared__ float s_score, s_denom;

    if (tid < 32) {
        int j = tid;
        float tcol[NLAB];
        #pragma unroll
        for (int i = 0; i < NLAB; i++) tcol[i] = (j < NLAB) ? trans[i * NLAB + j] : 0.f;
        float alpha = (j < NLAB) ? (start_t[j] + g_em[0][b][j]) : -1e30f;

        for (int t = 1; t < T; t++) {
            bool m = (sent[t * 64 + b] != 0);
            float em = (j < NLAB) ? g_em[t][b][j] : 0.f;
            float s[NLAB], mx = -1e30f;
            #pragma unroll
            for (int i = 0; i < NLAB; i++) {
                float ai = __shfl_sync(0xffffffffu, alpha, i);
                s[i] = ai + tcol[i];
                mx = fmaxf(mx, s[i]);
            }
            float sum = 0.f;
            #pragma unroll
            for (int i = 0; i < NLAB; i++) sum += __expf(s[i] - mx);
            float nxt = em + mx + __logf(sum);
            if (j < NLAB && m) alpha = nxt;
        }
        float v = (j < NLAB) ? (alpha + end_t[j]) : -1e30f;
        float mx = v;
        #pragma unroll
        for (int o = 16; o > 0; o >>= 1) mx = fmaxf(mx, __shfl_xor_sync(0xffffffffu, mx, o));
        float e = (j < NLAB) ? __expf(v - mx) : 0.f;
        #pragma unroll
        for (int o = 16; o > 0; o >>= 1) e += __shfl_xor_sync(0xffffffffu, e, o);
        if (tid == 0) s_denom = mx + __logf(e);
    } else {
        int l = tid - 32;
        float part = 0.f; int cnt = 0;
        for (int t = l; t < T; t += 32) {
            bool m = (sent[t * 64 + b] != 0);
            cnt += m ? 1 : 0;
            if (t >= 1 && m) {
                int tp = labels[(t - 1) * 64 + b];
                int tc = labels[t * 64 + b];
                part += trans[tp * NLAB + tc] + g_em[t][b][tc];
            }
        }
        #pragma unroll
        for (int o = 16; o > 0; o >>= 1) {
            part += __shfl_xor_sync(0xffffffffu, part, o);
            cnt  += __shfl_xor_sync(0xffffffffu, cnt, o);
        }
        if (l == 0) {
            int tag0 = labels[b];
            float score = start_t[tag0] + g_em[0][b][tag0] + part;
            int se = cnt - 1;
            int last = labels[se * 64 + b];
            score += end_t[last];
            s_score = score;
        }
    }
    __syncthreads();
    if (tid == 0) g_part[b] = s_denom - s_score;
}

__global__ void k_reduce(float* out)
{
    if (threadIdx.x == 0) {
        float s = 0.f;
        for (int b = 0; b < Bt; b++) s += g_part[b];
        out[0] = s;
    }
}

__global__ void k_reset()
{
    int i = threadIdx.x;
    if (i < 128) g_flags[i] = 0u;
}

// =============================================================================
extern "C" void kernel_launch(void* const* d_in, const int* in_sizes, int n_in,
                              void* d_out, int out_size)
{
    const float* emb    = (const float*)d_in[0];
    const float* Wih_f  = (const float*)d_in[1];
    const float* Whh_f  = (const float*)d_in[2];
    const float* b_f    = (const float*)d_in[3];
    const float* Wih_b  = (const float*)d_in[4];
    const float* Whh_b  = (const float*)d_in[5];
    const float* b_b    = (const float*)d_in[6];
    const float* W_top  = (const float*)d_in[7];
    const float* b_top  = (const float*)d_in[8];
    const float* startt = (const float*)d_in[9];
    const float* endt   = (const float*)d_in[10];
    const float* trans  = (const float*)d_in[11];
    const int*   sent   = (const int*)d_in[12];
    const int*   labels = (const int*)d_in[13];
    float* out = (float*)d_out;

    cudaFuncSetAttribute(k_lstm, cudaFuncAttributeMaxDynamicSharedMemorySize, LSTM_SMEM);
    cudaFuncSetAttribute(k_emis, cudaFuncAttributeMaxDynamicSharedMemorySize, 57344);

    k_reset<<<1, 128>>>();
    k_xproj<<<dim3(32, 256), 256>>>(emb, Wih_f, b_f, Wih_b, b_b, sent);
    k_lstm <<<128, 288, LSTM_SMEM>>>(Whh_f, Whh_b);
    k_emis <<<256, 256, 57344>>>(W_top, b_top);
    k_crf  <<<64, 64>>>(sent, labels, startt, endt, trans);
    k_reduce<<<1, 32>>>(out);
}

// round 15
// speedup vs baseline: 1.0216x; 1.0216x over previous
#include <cuda_runtime.h>
#include <cuda_bf16.h>
#include <cstdint>

#define T 256
#define Bt 64
#define EMB 300
#define HID 256
#define G4 1024
#define NLAB 20

typedef unsigned long long ull;

// ---------------- scratch ----------------
__device__ float g_xproj[2][T][G4][Bt];   // [dir][t][gate][batch]
__device__ float g_h[2][T][HID][Bt];      // [dir][t][hid][batch]
__device__ float g_em[T][Bt][NLAB];
__device__ float g_part[Bt];
__device__ unsigned g_flags[128];
__device__ unsigned g_rel;

// ---------------- f32x2 packed FMA (Blackwell) ----------------
__device__ __forceinline__ ull ffma2(ull a, ull b, ull c) {
    ull d;
    asm("fma.rn.f32x2 %0, %1, %2, %3;" : "=l"(d) : "l"(a), "l"(b), "l"(c));
    return d;
}
__device__ __forceinline__ float lo_hi_sum(ull v) {
    float2 f = *(float2*)&v;
    return f.x + f.y;
}

// ---------------- smem / async helpers ----------------
__device__ __forceinline__ uint32_t smem_u32(const void* p) {
    uint32_t a;
    asm("{ .reg .u64 t; cvta.to.shared.u64 t, %1; cvt.u32.u64 %0, t; }" : "=r"(a) : "l"(p));
    return a;
}
__device__ __forceinline__ void mbar_init(uint32_t mbar, uint32_t cnt) {
    asm volatile("mbarrier.init.shared.b64 [%0], %1;" :: "r"(mbar), "r"(cnt) : "memory");
}
__device__ __forceinline__ void mbar_expect_tx(uint32_t mbar, uint32_t bytes) {
    asm volatile("mbarrier.arrive.expect_tx.shared.b64 _, [%0], %1;" :: "r"(mbar), "r"(bytes) : "memory");
}
__device__ __forceinline__ void mbar_wait(uint32_t mbar, uint32_t phase) {
    asm volatile(
        "{\n\t.reg .pred P;\n"
        "WL_%=:\n\t"
        "mbarrier.try_wait.parity.shared.b64 P, [%0], %1;\n\t"
        "@!P bra WL_%=;\n\t}"
        :: "r"(mbar), "r"(phase) : "memory");
}
__device__ __forceinline__ void bulk_cp(uint32_t dst_smem, const void* src, uint32_t bytes, uint32_t mbar) {
    asm volatile(
        "cp.async.bulk.shared::cluster.global.mbarrier::complete_tx::bytes [%0], [%1], %2, [%3];"
        :: "r"(dst_smem), "l"(src), "r"(bytes), "r"(mbar) : "memory");
}
__device__ __forceinline__ void cp_async16(uint32_t dst, const void* src, uint32_t srcbytes) {
    asm volatile("cp.async.ca.shared.global [%0], [%1], 16, %2;"
                 :: "r"(dst), "l"(src), "r"(srcbytes) : "memory");
}
#define CP_COMMIT() asm volatile("cp.async.commit_group;" ::: "memory")
#define CP_WAIT1()  asm volatile("cp.async.wait_group 1;" ::: "memory")
#define CP_WAIT0()  asm volatile("cp.async.wait_group 0;" ::: "memory")

// =============================================================================
// Kernel 1: x_proj GEMM — R7 version (best measured): 64x64x32 tiles,
// 2-stage cp.async double buffer, f32x2 K-paired FMAs, 4x4 microtile.
// =============================================================================
__global__ void __launch_bounds__(256) k_xproj(
    const float* __restrict__ emb,
    const float* __restrict__ Wf, const float* __restrict__ bf,
    const float* __restrict__ Wb, const float* __restrict__ bb,
    const int*   __restrict__ sent)
{
    __shared__ float As[2][64 * 32];
    __shared__ float Bs[2][64 * 32];
    __shared__ int   ws[64];

    int t   = blockIdx.y;
    int n0  = blockIdx.x * 64;
    int dir = (n0 >= 1024) ? 1 : 0;
    const float* W    = dir ? Wb : Wf;
    const float* bias = dir ? bb : bf;
    int gbase = n0 & 1023;
    int tid = threadIdx.x;

    if (tid < 64) ws[tid] = sent[t * 64 + tid];
    __syncthreads();

    uint32_t as_base = smem_u32(&As[0][0]);
    uint32_t bs_base = smem_u32(&Bs[0][0]);

    int r0 = tid >> 3,          sl0 = tid & 7;
    int r1 = (tid + 256) >> 3,  sl1 = (tid + 256) & 7;
    uint32_t d0 = (uint32_t)(r0 * 128 + ((sl0 ^ (r0 & 7)) << 4));
    uint32_t d1 = (uint32_t)(r1 * 128 + ((sl1 ^ (r1 & 7)) << 4));
    const float* arow0 = emb + (size_t)ws[r0] * EMB;
    const float* arow1 = emb + (size_t)ws[r1] * EMB;
    const float* brow0 = W + (size_t)(gbase + r0) * EMB;
    const float* brow1 = W + (size_t)(gbase + r1) * EMB;

    auto issue = [&](int kt, int buf) {
        int k0 = kt * 32;
        uint32_t boff = (uint32_t)(buf * 8192);
        int kg0 = k0 + sl0 * 4, kg1 = k0 + sl1 * 4;
        uint32_t n0b = (kg0 + 4 <= EMB) ? 16u : 0u;
        uint32_t n1b = (kg1 + 4 <= EMB) ? 16u : 0u;
        cp_async16(as_base + boff + d0, arow0 + (n0b ? kg0 : 0), n0b);
        cp_async16(as_base + boff + d1, arow1 + (n1b ? kg1 : 0), n1b);
        cp_async16(bs_base + boff + d0, brow0 + (n0b ? kg0 : 0), n0b);
        cp_async16(bs_base + boff + d1, brow1 + (n1b ? kg1 : 0), n1b);
    };

    ull acc[4][4];
    #pragma unroll
    for (int i = 0; i < 4; i++)
        #pragma unroll
        for (int j = 0; j < 4; j++) acc[i][j] = 0ull;

    int tx = tid & 15;
    int ty = tid >> 4;
    int sa = tx & 7;
    int sb = ty & 7;

    issue(0, 0);
    CP_COMMIT();

    for (int kt = 0; kt < 10; kt++) {
        if (kt < 9) {
            issue(kt + 1, (kt + 1) & 1);
            CP_COMMIT();
            CP_WAIT1();
        } else {
            CP_WAIT0();
        }
        __syncthreads();

        const float* Ab = &As[kt & 1][0];
        const float* Bb = &Bs[kt & 1][0];
        #pragma unroll
        for (int c = 0; c < 8; c++) {
            ulonglong2 a[4], b[4];
            int ca = (c ^ sa) << 2;
            int cb = (c ^ sb) << 2;
            #pragma unroll
            for (int i = 0; i < 4; i++)
                a[i] = *(const ulonglong2*)&Ab[(tx + 16 * i) * 32 + ca];
            #pragma unroll
            for (int j = 0; j < 4; j++)
                b[j] = *(const ulonglong2*)&Bb[(ty + 16 * j) * 32 + cb];
            #pragma unroll
            for (int i = 0; i < 4; i++)
                #pragma unroll
                for (int j = 0; j < 4; j++) {
                    acc[i][j] = ffma2(a[i].x, b[j].x, acc[i][j]);
                    acc[i][j] = ffma2(a[i].y, b[j].y, acc[i][j]);
                }
        }
        __syncthreads();
    }

    #pragma unroll
    for (int j = 0; j < 4; j++) {
        int g = gbase + ty + 16 * j;
        float bv = bias[g];
        #pragma unroll
        for (int i = 0; i < 4; i++) {
            int m = tx + 16 * i;
            g_xproj[dir][t][g][m] = lo_hi_sum(acc[i][j]) + bv;
        }
    }
}

// =============================================================================
// Kernel 2: persistent bidirectional LSTM — EXACT R13 version (2100us best),
// replay-invariant barrier. Launched TWICE this round for component timing:
//   lstm_us = total_us - 2100.5
// =============================================================================
__device__ __forceinline__ float sigf(float x) { return 1.f / (1.f + __expf(-x)); }

__device__ __forceinline__ void grid_barrier2(int bx, int tid, unsigned target)
{
    __threadfence();
    __syncthreads();
    if (tid == 0) ((volatile unsigned*)g_flags)[bx] = target;
    if (bx == 0) {
        if (tid < 32) {
            volatile unsigned* f = g_flags;
            for (;;) {
                bool ok = (f[tid] >= target) & (f[tid + 32] >= target)
                        & (f[tid + 64] >= target) & (f[tid + 96] >= target);
                if (__all_sync(0xffffffffu, ok)) break;
            }
            if (tid == 0) {
                __threadfence();
                *(volatile unsigned*)&g_rel = target;
            }
        }
    } else if (tid == 0) {
        volatile unsigned* r = &g_rel;
        while (*r < target) {}
    }
    __syncthreads();
}

// smem: Ws2 32KB | hs 64KB | red 32KB | mbars
#define LSTM_SMEM (32768 + 65536 + 32768 + 64)

__global__ void __launch_bounds__(256) k_lstm(
    const float* __restrict__ Whf, const float* __restrict__ Whb)
{
    extern __shared__ float sm[];
    ull*   Ws2 = (ull*)sm;                  // [k=256][16 gates] dup-pairs, 32KB
    float* hs  = sm + 8192;                 // [k=256][b=64], 64KB
    float* red = sm + 8192 + 16384;         // [ks=8][gi=16][b=64], 32KB
    uint32_t mbar0 = smem_u32(sm + 32768);  // 4 mbarriers

    int bx  = blockIdx.x;
    int dir = bx >> 6;
    int cc  = bx & 63;
    const float* Whh = dir ? Whb : Whf;
    int tid = threadIdx.x;

    // replay-invariant base: all flags are uniform at kernel entry.
    unsigned base0 = ((volatile unsigned*)g_flags)[bx];

    for (int idx = tid; idx < 4096; idx += 256) {
        int k = idx & 255, r = idx >> 8;
        int q = r >> 2, j = r & 3;
        float w = Whh[(q * 256 + 4 * cc + j) * HID + k];
        float2 w2 = make_float2(w, w);
        Ws2[k * 16 + r] = *(ull*)&w2;
    }
    if (tid == 0)
        for (int ch = 0; ch < 4; ch++) mbar_init(mbar0 + ch * 8, 1);
    __syncthreads();

    int lane = tid & 31;
    int ks   = tid >> 5;
    int gq   = lane >> 3;
    int bq   = lane & 7;
    int kbase = ks * 32;
    uint32_t my_mbar = mbar0 + (ks >> 1) * 8;

    int jrow = tid >> 6;
    int bcol = tid & 63;
    float cstate = 0.f;

    float* hb = &g_h[dir][0][0][0];
    uint32_t hs_smem = smem_u32(hs);

    for (int step = 0; step < T; step++) {
        int t = dir ? (T - 1 - step) : step;

        if (step > 0 && tid == 0) {
            int tprev = dir ? (t + 1) : (t - 1);
            const float* src = hb + tprev * HID * Bt;
            #pragma unroll
            for (int ch = 0; ch < 4; ch++) {
                mbar_expect_tx(mbar0 + ch * 8, 16384);
                bulk_cp(hs_smem + ch * 16384, src + ch * 4096, 16384, mbar0 + ch * 8);
            }
        }

        float xp[4];
        #pragma unroll
        for (int q2 = 0; q2 < 4; q2++)
            xp[q2] = g_xproj[dir][t][q2 * 256 + 4 * cc + jrow][bcol];

        ull acc[4][4];
        #pragma unroll
        for (int j = 0; j < 4; j++)
            #pragma unroll
            for (int p = 0; p < 4; p++) acc[j][p] = 0ull;

        if (step > 0) {
            mbar_wait(my_mbar, (unsigned)(step - 1) & 1u);
            #pragma unroll 8
            for (int kk = 0; kk < 32; kk++) {
                int k = kbase + kk;
                const ull* wrow = Ws2 + k * 16 + gq * 4;
                ulonglong2 wv0 = *(const ulonglong2*)wrow;
                ulonglong2 wv1 = *(const ulonglong2*)(wrow + 2);
                const float* hrow = hs + k * 64 + bq * 8;
                ulonglong2 ha  = *(const ulonglong2*)hrow;
                ulonglong2 hb2 = *(const ulonglong2*)(hrow + 4);
                acc[0][0] = ffma2(wv0.x, ha.x,  acc[0][0]);
                acc[0][1] = ffma2(wv0.x, ha.y,  acc[0][1]);
                acc[0][2] = ffma2(wv0.x, hb2.x, acc[0][2]);
                acc[0][3] = ffma2(wv0.x, hb2.y, acc[0][3]);
                acc[1][0] = ffma2(wv0.y, ha.x,  acc[1][0]);
                acc[1][1] = ffma2(wv0.y, ha.y,  acc[1][1]);
                acc[1][2] = ffma2(wv0.y, hb2.x, acc[1][2]);
                acc[1][3] = ffma2(wv0.y, hb2.y, acc[1][3]);
                acc[2][0] = ffma2(wv1.x, ha.x,  acc[2][0]);
                acc[2][1] = ffma2(wv1.x, ha.y,  acc[2][1]);
                acc[2][2] = ffma2(wv1.x, hb2.x, acc[2][2]);
                acc[2][3] = ffma2(wv1.x, hb2.y, acc[2][3]);
                acc[3][0] = ffma2(wv1.y, ha.x,  acc[3][0]);
                acc[3][1] = ffma2(wv1.y, ha.y,  acc[3][1]);
                acc[3][2] = ffma2(wv1.y, hb2.x, acc[3][2]);
                acc[3][3] = ffma2(wv1.y, hb2.y, acc[3][3]);
            }
        }

        {
            float* rrow = red + (ks * 16 + gq * 4) * 64 + bq * 8;
            #pragma unroll
            for (int j = 0; j < 4; j++) {
                ulonglong2 v0; v0.x = acc[j][0]; v0.y = acc[j][1];
                ulonglong2 v1; v1.x = acc[j][2]; v1.y = acc[j][3];
                *(ulonglong2*)(rrow + j * 64)     = v0;
                *(ulonglong2*)(rrow + j * 64 + 4) = v1;
            }
        }
        __syncthreads();

        float iv = xp[0], fv = xp[1], gv = xp[2], ov = xp[3];
        #pragma unroll
        for (int s = 0; s < 8; s++) {
            iv += red[(s * 16 +  0 + jrow) * 64 + bcol];
            fv += red[(s * 16 +  4 + jrow) * 64 + bcol];
            gv += red[(s * 16 +  8 + jrow) * 64 + bcol];
            ov += red[(s * 16 + 12 + jrow) * 64 + bcol];
        }
        cstate = sigf(fv) * cstate + sigf(iv) * tanhf(gv);
        float hv = sigf(ov) * tanhf(cstate);
        hb[t * HID * Bt + (4 * cc + jrow) * Bt + bcol] = hv;

        grid_barrier2(bx, tid, base0 + (unsigned)(step + 1));
    }
}

// =============================================================================
// Kernel 3: emissions
// =============================================================================
__global__ void __launch_bounds__(256) k_emis(
    const float* __restrict__ Wt, const float* __restrict__ bt)
{
    extern __shared__ float sm[];
    float* Wts = sm;
    float* hch = sm + 10240;

    int t = blockIdx.x, tid = threadIdx.x;
    for (int i = tid; i < NLAB * 2 * HID; i += 256) Wts[i] = Wt[i];

    float acc[5] = {0.f, 0.f, 0.f, 0.f, 0.f};
    int b = tid & 63;
    int lbase = tid >> 6;

    for (int d = 0; d < 2; d++) {
        const float* hsrc = &g_h[d][t][0][0];
        for (int jc = 0; jc < 4; jc++) {
            __syncthreads();
            for (int i = tid; i < 4096; i += 256) hch[i] = hsrc[jc * 4096 + i];
            __syncthreads();
            #pragma unroll 4
            for (int j2 = 0; j2 < 64; j2++) {
                float hv = hch[j2 * 64 + b];
                #pragma unroll
                for (int s = 0; s < 5; s++) {
                    int l = lbase + 4 * s;
                    acc[s] += hv * Wts[l * 2 * HID + d * HID + jc * 64 + j2];
                }
            }
        }
    }
    #pragma unroll
    for (int s = 0; s < 5; s++) {
        int l = lbase + 4 * s;
        g_em[t][b][l] = acc[s] + bt[l];
    }
}

// =============================================================================
// Kernel 4: CRF per batch
// =============================================================================
__global__ void __launch_bounds__(64) k_crf(
    const int* __restrict__ sent, const int* __restrict__ labels,
    const float* __restrict__ start_t, const float* __restrict__ end_t,
    const float* __restrict__ trans)
{
    int b = blockIdx.x;
    int tid = threadIdx.x;
    __shared__ float s_score, s_denom;

    if (tid < 32) {
        int j = tid;
        float tcol[NLAB];
        #pragma unroll
        for (int i = 0; i < NLAB; i++) tcol[i] = (j < NLAB) ? trans[i * NLAB + j] : 0.f;
        float alpha = (j < NLAB) ? (start_t[j] + g_em[0][b][j]) : -1e30f;

        for (int t = 1; t < T; t++) {
            bool m = (sent[t * 64 + b] != 0);
            float em = (j < NLAB) ? g_em[t][b][j] : 0.f;
            float s[NLAB], mx = -1e30f;
            #pragma unroll
            for (int i = 0; i < NLAB; i++) {
                float ai = __shfl_sync(0xffffffffu, alpha, i);
                s[i] = ai + tcol[i];
                mx = fmaxf(mx, s[i]);
            }
            float sum = 0.f;
            #pragma unroll
            for (int i = 0; i < NLAB; i++) sum += __expf(s[i] - mx);
            float nxt = em + mx + __logf(sum);
            if (j < NLAB && m) alpha = nxt;
        }
        float v = (j < NLAB) ? (alpha + end_t[j]) : -1e30f;
        float mx = v;
        #pragma unroll
        for (int o = 16; o > 0; o >>= 1) mx = fmaxf(mx, __shfl_xor_sync(0xffffffffu, mx, o));
        float e = (j < NLAB) ? __expf(v - mx) : 0.f;
        #pragma unroll
        for (int o = 16; o > 0; o >>= 1) e += __shfl_xor_sync(0xffffffffu, e, o);
        if (tid == 0) s_denom = mx + __logf(e);
    } else {
        int l = tid - 32;
        float part = 0.f; int cnt = 0;
        for (int t = l; t < T; t += 32) {
            bool m = (sent[t * 64 + b] != 0);
            cnt += m ? 1 : 0;
            if (t >= 1 && m) {
                int tp = labels[(t - 1) * 64 + b];
                int tc = labels[t * 64 + b];
                part += trans[tp * NLAB + tc] + g_em[t][b][tc];
            }
        }
        #pragma unroll
        for (int o = 16; o > 0; o >>= 1) {
            part += __shfl_xor_sync(0xffffffffu, part, o);
            cnt  += __shfl_xor_sync(0xffffffffu, cnt, o);
        }
        if (l == 0) {
            int tag0 = labels[b];
            float score = start_t[tag0] + g_em[0][b][tag0] + part;
            int se = cnt - 1;
            int last = labels[se * 64 + b];
            score += end_t[last];
            s_score = score;
        }
    }
    __syncthreads();
    if (tid == 0) g_part[b] = s_denom - s_score;
}

__global__ void k_reduce(float* out)
{
    if (threadIdx.x == 0) {
        float s = 0.f;
        for (int b = 0; b < Bt; b++) s += g_part[b];
        out[0] = s;
    }
}

__global__ void k_reset()
{
    int i = threadIdx.x;
    if (i < 128) g_flags[i] = 0u;
    if (i == 0)  g_rel = 0u;
}

// =============================================================================
extern "C" void kernel_launch(void* const* d_in, const int* in_sizes, int n_in,
                              void* d_out, int out_size)
{
    const float* emb    = (const float*)d_in[0];
    const float* Wih_f  = (const float*)d_in[1];
    const float* Whh_f  = (const float*)d_in[2];
    const float* b_f    = (const float*)d_in[3];
    const float* Wih_b  = (const float*)d_in[4];
    const float* Whh_b  = (const float*)d_in[5];
    const float* b_b    = (const float*)d_in[6];
    const float* W_top  = (const float*)d_in[7];
    const float* b_top  = (const float*)d_in[8];
    const float* startt = (const float*)d_in[9];
    const float* endt   = (const float*)d_in[10];
    const float* trans  = (const float*)d_in[11];
    const int*   sent   = (const int*)d_in[12];
    const int*   labels = (const int*)d_in[13];
    float* out = (float*)d_out;

    cudaFuncSetAttribute(k_lstm, cudaFuncAttributeMaxDynamicSharedMemorySize, LSTM_SMEM);
    cudaFuncSetAttribute(k_emis, cudaFuncAttributeMaxDynamicSharedMemorySize, 57344);

    k_reset<<<1, 128>>>();
    k_xproj<<<dim3(32, 256), 256>>>(emb, Wih_f, b_f, Wih_b, b_b, sent);
    // k_lstm launched TWICE: second run recomputes identical h (deterministic).
    // Component timing: lstm_us = total_us - 2100.5 (R13 single-launch total).
    k_lstm <<<128, 256, LSTM_SMEM>>>(Whh_f, Whh_b);
    k_lstm <<<128, 256, LSTM_SMEM>>>(Whh_f, Whh_b);
    k_emis <<<256, 256, 57344>>>(W_top, b_top);
    k_crf  <<<64, 64>>>(sent, labels, startt, endt, trans);
    k_reduce<<<1, 32>>>(out);
}

// round 16
// speedup vs baseline: 1.5077x; 1.4758x over previous
#include <cuda_runtime.h>
#include <cuda_bf16.h>
#include <cstdint>

#define T 256
#define Bt 64
#define EMB 300
#define HID 256
#define G4 1024
#define NLAB 20

typedef unsigned long long ull;

// ---------------- scratch ----------------
__device__ float g_xproj[2][T][G4][Bt];   // [dir][t][gate][batch]
__device__ float g_h[2][T][HID][Bt];      // [dir][t][hid][batch]
__device__ float g_em[T][Bt][NLAB];
__device__ float g_part[Bt];
__device__ __align__(16) unsigned g_flags[128];
__device__ unsigned g_rel;

// ---------------- f32x2 packed FMA (Blackwell) ----------------
__device__ __forceinline__ ull ffma2(ull a, ull b, ull c) {
    ull d;
    asm("fma.rn.f32x2 %0, %1, %2, %3;" : "=l"(d) : "l"(a), "l"(b), "l"(c));
    return d;
}
__device__ __forceinline__ float lo_hi_sum(ull v) {
    float2 f = *(float2*)&v;
    return f.x + f.y;
}

// ---------------- smem / async helpers ----------------
__device__ __forceinline__ uint32_t smem_u32(const void* p) {
    uint32_t a;
    asm("{ .reg .u64 t; cvta.to.shared.u64 t, %1; cvt.u32.u64 %0, t; }" : "=r"(a) : "l"(p));
    return a;
}
__device__ __forceinline__ void mbar_init(uint32_t mbar, uint32_t cnt) {
    asm volatile("mbarrier.init.shared.b64 [%0], %1;" :: "r"(mbar), "r"(cnt) : "memory");
}
__device__ __forceinline__ void mbar_expect_tx(uint32_t mbar, uint32_t bytes) {
    asm volatile("mbarrier.arrive.expect_tx.shared.b64 _, [%0], %1;" :: "r"(mbar), "r"(bytes) : "memory");
}
__device__ __forceinline__ void mbar_wait(uint32_t mbar, uint32_t phase) {
    asm volatile(
        "{\n\t.reg .pred P;\n"
        "WL_%=:\n\t"
        "mbarrier.try_wait.parity.shared.b64 P, [%0], %1;\n\t"
        "@!P bra WL_%=;\n\t}"
        :: "r"(mbar), "r"(phase) : "memory");
}
__device__ __forceinline__ void bulk_cp(uint32_t dst_smem, const void* src, uint32_t bytes, uint32_t mbar) {
    asm volatile(
        "cp.async.bulk.shared::cluster.global.mbarrier::complete_tx::bytes [%0], [%1], %2, [%3];"
        :: "r"(dst_smem), "l"(src), "r"(bytes), "r"(mbar) : "memory");
}
__device__ __forceinline__ void cp_async16(uint32_t dst, const void* src, uint32_t srcbytes) {
    asm volatile("cp.async.ca.shared.global [%0], [%1], 16, %2;"
                 :: "r"(dst), "l"(src), "r"(srcbytes) : "memory");
}
#define CP_COMMIT() asm volatile("cp.async.commit_group;" ::: "memory")
#define CP_WAIT1()  asm volatile("cp.async.wait_group 1;" ::: "memory")
#define CP_WAIT0()  asm volatile("cp.async.wait_group 0;" ::: "memory")

// L2-served wide volatile load (NOT __ldcv: .cv bypasses L2 -> DRAM RTT).
__device__ __forceinline__ uint4 ld_vol4(const unsigned* p) {
    uint4 v;
    asm volatile("ld.volatile.global.v4.u32 {%0,%1,%2,%3}, [%4];"
                 : "=r"(v.x), "=r"(v.y), "=r"(v.z), "=r"(v.w) : "l"(p) : "memory");
    return v;
}

// =============================================================================
// Kernel 1: x_proj GEMM — R7 version (best measured).
// =============================================================================
__global__ void __launch_bounds__(256) k_xproj(
    const float* __restrict__ emb,
    const float* __restrict__ Wf, const float* __restrict__ bf,
    const float* __restrict__ Wb, const float* __restrict__ bb,
    const int*   __restrict__ sent)
{
    __shared__ float As[2][64 * 32];
    __shared__ float Bs[2][64 * 32];
    __shared__ int   ws[64];

    int t   = blockIdx.y;
    int n0  = blockIdx.x * 64;
    int dir = (n0 >= 1024) ? 1 : 0;
    const float* W    = dir ? Wb : Wf;
    const float* bias = dir ? bb : bf;
    int gbase = n0 & 1023;
    int tid = threadIdx.x;

    if (tid < 64) ws[tid] = sent[t * 64 + tid];
    __syncthreads();

    uint32_t as_base = smem_u32(&As[0][0]);
    uint32_t bs_base = smem_u32(&Bs[0][0]);

    int r0 = tid >> 3,          sl0 = tid & 7;
    int r1 = (tid + 256) >> 3,  sl1 = (tid + 256) & 7;
    uint32_t d0 = (uint32_t)(r0 * 128 + ((sl0 ^ (r0 & 7)) << 4));
    uint32_t d1 = (uint32_t)(r1 * 128 + ((sl1 ^ (r1 & 7)) << 4));
    const float* arow0 = emb + (size_t)ws[r0] * EMB;
    const float* arow1 = emb + (size_t)ws[r1] * EMB;
    const float* brow0 = W + (size_t)(gbase + r0) * EMB;
    const float* brow1 = W + (size_t)(gbase + r1) * EMB;

    auto issue = [&](int kt, int buf) {
        int k0 = kt * 32;
        uint32_t boff = (uint32_t)(buf * 8192);
        int kg0 = k0 + sl0 * 4, kg1 = k0 + sl1 * 4;
        uint32_t n0b = (kg0 + 4 <= EMB) ? 16u : 0u;
        uint32_t n1b = (kg1 + 4 <= EMB) ? 16u : 0u;
        cp_async16(as_base + boff + d0, arow0 + (n0b ? kg0 : 0), n0b);
        cp_async16(as_base + boff + d1, arow1 + (n1b ? kg1 : 0), n1b);
        cp_async16(bs_base + boff + d0, brow0 + (n0b ? kg0 : 0), n0b);
        cp_async16(bs_base + boff + d1, brow1 + (n1b ? kg1 : 0), n1b);
    };

    ull acc[4][4];
    #pragma unroll
    for (int i = 0; i < 4; i++)
        #pragma unroll
        for (int j = 0; j < 4; j++) acc[i][j] = 0ull;

    int tx = tid & 15;
    int ty = tid >> 4;
    int sa = tx & 7;
    int sb = ty & 7;

    issue(0, 0);
    CP_COMMIT();

    for (int kt = 0; kt < 10; kt++) {
        if (kt < 9) {
            issue(kt + 1, (kt + 1) & 1);
            CP_COMMIT();
            CP_WAIT1();
        } else {
            CP_WAIT0();
        }
        __syncthreads();

        const float* Ab = &As[kt & 1][0];
        const float* Bb = &Bs[kt & 1][0];
        #pragma unroll
        for (int c = 0; c < 8; c++) {
            ulonglong2 a[4], b[4];
            int ca = (c ^ sa) << 2;
            int cb = (c ^ sb) << 2;
            #pragma unroll
            for (int i = 0; i < 4; i++)
                a[i] = *(const ulonglong2*)&Ab[(tx + 16 * i) * 32 + ca];
            #pragma unroll
            for (int j = 0; j < 4; j++)
                b[j] = *(const ulonglong2*)&Bs[kt & 1][(ty + 16 * j) * 32 + cb];
            #pragma unroll
            for (int i = 0; i < 4; i++)
                #pragma unroll
                for (int j = 0; j < 4; j++) {
                    acc[i][j] = ffma2(a[i].x, b[j].x, acc[i][j]);
                    acc[i][j] = ffma2(a[i].y, b[j].y, acc[i][j]);
                }
        }
        __syncthreads();
    }

    #pragma unroll
    for (int j = 0; j < 4; j++) {
        int g = gbase + ty + 16 * j;
        float bv = bias[g];
        #pragma unroll
        for (int i = 0; i < 4; i++) {
            int m = tx + 16 * i;
            g_xproj[dir][t][g][m] = lo_hi_sum(acc[i][j]) + bv;
        }
    }
}

// =============================================================================
// Kernel 2: persistent bidirectional LSTM — low-latency barrier:
//  - publish after the (single) post-act syncthreads; fence by tid0 only
//  - CTA0 warp0 polls all 128 flags via ld.volatile.v4 (4 L2 lines, 1 warp)
//  - no barrier-exit syncthreads: warps re-sync on their chunk mbarrier;
//    tid0 polls release + issues next step's TMAs at the step tail.
// =============================================================================
__device__ __forceinline__ float sigf(float x) { return 1.f / (1.f + __expf(-x)); }

// smem: Ws2 32KB | hs 64KB | red 32KB | mbars
#define LSTM_SMEM (32768 + 65536 + 32768 + 64)

__global__ void __launch_bounds__(256) k_lstm(
    const float* __restrict__ Whf, const float* __restrict__ Whb)
{
    extern __shared__ float sm[];
    ull*   Ws2 = (ull*)sm;                  // [k=256][16 gates] dup-pairs, 32KB
    float* hs  = sm + 8192;                 // [k=256][b=64], 64KB
    float* red = sm + 8192 + 16384;         // [ks=8][gi=16][b=64], 32KB
    uint32_t mbar0 = smem_u32(sm + 32768);  // 4 mbarriers

    int bx  = blockIdx.x;
    int dir = bx >> 6;
    int cc  = bx & 63;
    const float* Whh = dir ? Whb : Whf;
    int tid = threadIdx.x;

    // replay-invariant base: all flags are uniform at kernel entry.
    unsigned base0 = ((volatile unsigned*)g_flags)[bx];

    for (int idx = tid; idx < 4096; idx += 256) {
        int k = idx & 255, r = idx >> 8;
        int q = r >> 2, j = r & 3;
        float w = Whh[(q * 256 + 4 * cc + j) * HID + k];
        float2 w2 = make_float2(w, w);
        Ws2[k * 16 + r] = *(ull*)&w2;
    }
    if (tid == 0)
        for (int ch = 0; ch < 4; ch++) mbar_init(mbar0 + ch * 8, 1);
    __syncthreads();

    int lane = tid & 31;
    int ks   = tid >> 5;
    int gq   = lane >> 3;
    int bq   = lane & 7;
    int kbase = ks * 32;
    uint32_t my_mbar = mbar0 + (ks >> 1) * 8;

    int jrow = tid >> 6;
    int bcol = tid & 63;
    float cstate = 0.f;

    float* hb = &g_h[dir][0][0][0];
    uint32_t hs_smem = smem_u32(hs);
    const unsigned* fpoll = g_flags + lane * 4;   // leader: 32 lanes x 4 flags

    for (int step = 0; step < T; step++) {
        int t = dir ? (T - 1 - step) : step;

        // prefetch x_proj for this step's activation
        float xp[4];
        #pragma unroll
        for (int q2 = 0; q2 < 4; q2++)
            xp[q2] = g_xproj[dir][t][q2 * 256 + 4 * cc + jrow][bcol];

        ull acc[4][4];
        #pragma unroll
        for (int j = 0; j < 4; j++)
            #pragma unroll
            for (int p = 0; p < 4; p++) acc[j][p] = 0ull;

        if (step > 0) {
            mbar_wait(my_mbar, (unsigned)(step - 1) & 1u);
            #pragma unroll 8
            for (int kk = 0; kk < 32; kk++) {
                int k = kbase + kk;
                const ull* wrow = Ws2 + k * 16 + gq * 4;
                ulonglong2 wv0 = *(const ulonglong2*)wrow;
                ulonglong2 wv1 = *(const ulonglong2*)(wrow + 2);
                const float* hrow = hs + k * 64 + bq * 8;
                ulonglong2 ha  = *(const ulonglong2*)hrow;
                ulonglong2 hb2 = *(const ulonglong2*)(hrow + 4);
                acc[0][0] = ffma2(wv0.x, ha.x,  acc[0][0]);
                acc[0][1] = ffma2(wv0.x, ha.y,  acc[0][1]);
                acc[0][2] = ffma2(wv0.x, hb2.x, acc[0][2]);
                acc[0][3] = ffma2(wv0.x, hb2.y, acc[0][3]);
                acc[1][0] = ffma2(wv0.y, ha.x,  acc[1][0]);
                acc[1][1] = ffma2(wv0.y, ha.y,  acc[1][1]);
                acc[1][2] = ffma2(wv0.y, hb2.x, acc[1][2]);
                acc[1][3] = ffma2(wv0.y, hb2.y, acc[1][3]);
                acc[2][0] = ffma2(wv1.x, ha.x,  acc[2][0]);
                acc[2][1] = ffma2(wv1.x, ha.y,  acc[2][1]);
                acc[2][2] = ffma2(wv1.x, hb2.x, acc[2][2]);
                acc[2][3] = ffma2(wv1.x, hb2.y, acc[2][3]);
                acc[3][0] = ffma2(wv1.y, ha.x,  acc[3][0]);
                acc[3][1] = ffma2(wv1.y, ha.y,  acc[3][1]);
                acc[3][2] = ffma2(wv1.y, hb2.x, acc[3][2]);
                acc[3][3] = ffma2(wv1.y, hb2.y, acc[3][3]);
            }
        }

        {
            float* rrow = red + (ks * 16 + gq * 4) * 64 + bq * 8;
            #pragma unroll
            for (int j = 0; j < 4; j++) {
                ulonglong2 v0; v0.x = acc[j][0]; v0.y = acc[j][1];
                ulonglong2 v1; v1.x = acc[j][2]; v1.y = acc[j][3];
                *(ulonglong2*)(rrow + j * 64)     = v0;
                *(ulonglong2*)(rrow + j * 64 + 4) = v1;
            }
        }
        __syncthreads();

        float iv = xp[0], fv = xp[1], gv = xp[2], ov = xp[3];
        #pragma unroll
        for (int s = 0; s < 8; s++) {
            iv += red[(s * 16 +  0 + jrow) * 64 + bcol];
            fv += red[(s * 16 +  4 + jrow) * 64 + bcol];
            gv += red[(s * 16 +  8 + jrow) * 64 + bcol];
            ov += red[(s * 16 + 12 + jrow) * 64 + bcol];
        }
        cstate = sigf(fv) * cstate + sigf(iv) * tanhf(gv);
        float hv = sigf(ov) * tanhf(cstate);
        hb[t * HID * Bt + (4 * cc + jrow) * Bt + bcol] = hv;

        // all warps done reading hs/red and writing h
        __syncthreads();

        unsigned tgt = base0 + (unsigned)(step + 1);
        if (tid == 0) {
            __threadfence();                       // h stores -> L2 before flag
            ((volatile unsigned*)g_flags)[bx] = tgt;
        }

        if (step < T - 1) {
            if (bx == 0 && tid < 32) {
                // leader: one v4 load per lane covers all 128 flags
                for (;;) {
                    uint4 v = ld_vol4(fpoll);
                    bool ok = (v.x >= tgt) & (v.y >= tgt) &
                              (v.z >= tgt) & (v.w >= tgt);
                    if (__all_sync(0xffffffffu, ok)) break;
                }
                if (tid == 0) {
                    __threadfence();
                    *(volatile unsigned*)&g_rel = tgt;
                }
            }
            if (tid == 0) {
                if (bx != 0) {
                    volatile unsigned* r = &g_rel;
                    while (*r < tgt) {}
                }
                // issue next step's h broadcast; other warps are already
                // parked on their chunk mbarriers.
                int tnext = dir ? (t - 1) : (t + 1);   // h produced this step
                const float* src = hb + t * HID * Bt;  // h(t) just written
                (void)tnext;
                #pragma unroll
                for (int ch = 0; ch < 4; ch++) {
                    mbar_expect_tx(mbar0 + ch * 8, 16384);
                    bulk_cp(hs_smem + ch * 16384, src + ch * 4096, 16384, mbar0 + ch * 8);
                }
            }
        }
    }
}

// =============================================================================
// Kernel 3: emissions
// =============================================================================
__global__ void __launch_bounds__(256) k_emis(
    const float* __restrict__ Wt, const float* __restrict__ bt)
{
    extern __shared__ float sm[];
    float* Wts = sm;
    float* hch = sm + 10240;

    int t = blockIdx.x, tid = threadIdx.x;
    for (int i = tid; i < NLAB * 2 * HID; i += 256) Wts[i] = Wt[i];

    float acc[5] = {0.f, 0.f, 0.f, 0.f, 0.f};
    int b = tid & 63;
    int lbase = tid >> 6;

    for (int d = 0; d < 2; d++) {
        const float* hsrc = &g_h[d][t][0][0];
        for (int jc = 0; jc < 4; jc++) {
            __syncthreads();
            for (int i = tid; i < 4096; i += 256) hch[i] = hsrc[jc * 4096 + i];
            __syncthreads();
            #pragma unroll 4
            for (int j2 = 0; j2 < 64; j2++) {
                float hv = hch[j2 * 64 + b];
                #pragma unroll
                for (int s = 0; s < 5; s++) {
                    int l = lbase + 4 * s;
                    acc[s] += hv * Wts[l * 2 * HID + d * HID + jc * 64 + j2];
                }
            }
        }
    }
    #pragma unroll
    for (int s = 0; s < 5; s++) {
        int l = lbase + 4 * s;
        g_em[t][b][l] = acc[s] + bt[l];
    }
}

// =============================================================================
// Kernel 4: CRF per batch
// =============================================================================
__global__ void __launch_bounds__(64) k_crf(
    const int* __restrict__ sent, const int* __restrict__ labels,
    const float* __restrict__ start_t, const float* __restrict__ end_t,
    const float* __restrict__ trans)
{
    int b = blockIdx.x;
    int tid = threadIdx.x;
    __shared__ float s_score, s_denom;

    if (tid < 32) {
        int j = tid;
        float tcol[NLAB];
        #pragma unroll
        for (int i = 0; i < NLAB; i++) tcol[i] = (j < NLAB) ? trans[i * NLAB + j] : 0.f;
        float alpha = (j < NLAB) ? (start_t[j] + g_em[0][b][j]) : -1e30f;

        for (int t = 1; t < T; t++) {
            bool m = (sent[t * 64 + b] != 0);
            float em = (j < NLAB) ? g_em[t][b][j] : 0.f;
            float s[NLAB], mx = -1e30f;
            #pragma unroll
            for (int i = 0; i < NLAB; i++) {
                float ai = __shfl_sync(0xffffffffu, alpha, i);
                s[i] = ai + tcol[i];
                mx = fmaxf(mx, s[i]);
            }
            float sum = 0.f;
            #pragma unroll
            for (int i = 0; i < NLAB; i++) sum += __expf(s[i] - mx);
            float nxt = em + mx + __logf(sum);
            if (j < NLAB && m) alpha = nxt;
        }
        float v = (j < NLAB) ? (alpha + end_t[j]) : -1e30f;
        float mx = v;
        #pragma unroll
        for (int o = 16; o > 0; o >>= 1) mx = fmaxf(mx, __shfl_xor_sync(0xffffffffu, mx, o));
        float e = (j < NLAB) ? __expf(v - mx) : 0.f;
        #pragma unroll
        for (int o = 16; o > 0; o >>= 1) e += __shfl_xor_sync(0xffffffffu, e, o);
        if (tid == 0) s_denom = mx + __logf(e);
    } else {
        int l = tid - 32;
        float part = 0.f; int cnt = 0;
        for (int t = l; t < T; t += 32) {
            bool m = (sent[t * 64 + b] != 0);
            cnt += m ? 1 : 0;
            if (t >= 1 && m) {
                int tp = labels[(t - 1) * 64 + b];
                int tc = labels[t * 64 + b];
                part += trans[tp * NLAB + tc] + g_em[t][b][tc];
            }
        }
        #pragma unroll
        for (int o = 16; o > 0; o >>= 1) {
            part += __shfl_xor_sync(0xffffffffu, part, o);
            cnt  += __shfl_xor_sync(0xffffffffu, cnt, o);
        }
        if (l == 0) {
            int tag0 = labels[b];
            float score = start_t[tag0] + g_em[0][b][tag0] + part;
            int se = cnt - 1;
            int last = labels[se * 64 + b];
            score += end_t[last];
            s_score = score;
        }
    }
    __syncthreads();
    if (tid == 0) g_part[b] = s_denom - s_score;
}

__global__ void k_reduce(float* out)
{
    if (threadIdx.x == 0) {
        float s = 0.f;
        for (int b = 0; b < Bt; b++) s += g_part[b];
        out[0] = s;
    }
}

__global__ void k_reset()
{
    int i = threadIdx.x;
    if (i < 128) g_flags[i] = 0u;
    if (i == 0)  g_rel = 0u;
}

// =============================================================================
extern "C" void kernel_launch(void* const* d_in, const int* in_sizes, int n_in,
                              void* d_out, int out_size)
{
    const float* emb    = (const float*)d_in[0];
    const float* Wih_f  = (const float*)d_in[1];
    const float* Whh_f  = (const float*)d_in[2];
    const float* b_f    = (const float*)d_in[3];
    const float* Wih_b  = (const float*)d_in[4];
    const float* Whh_b  = (const float*)d_in[5];
    const float* b_b    = (const float*)d_in[6];
    const float* W_top  = (const float*)d_in[7];
    const float* b_top  = (const float*)d_in[8];
    const float* startt = (const float*)d_in[9];
    const float* endt   = (const float*)d_in[10];
    const float* trans  = (const float*)d_in[11];
    const int*   sent   = (const int*)d_in[12];
    const int*   labels = (const int*)d_in[13];
    float* out = (float*)d_out;

    cudaFuncSetAttribute(k_lstm, cudaFuncAttributeMaxDynamicSharedMemorySize, LSTM_SMEM);
    cudaFuncSetAttribute(k_emis, cudaFuncAttributeMaxDynamicSharedMemorySize, 57344);

    k_reset<<<1, 128>>>();
    k_xproj<<<dim3(32, 256), 256>>>(emb, Wih_f, b_f, Wih_b, b_b, sent);
    k_lstm <<<128, 256, LSTM_SMEM>>>(Whh_f, Whh_b);
    k_emis <<<256, 256, 57344>>>(W_top, b_top);
    k_crf  <<<64, 64>>>(sent, labels, startt, endt, trans);
    k_reduce<<<1, 32>>>(out);
}

// round 17
// speedup vs baseline: 1.8173x; 1.2054x over previous
#include <cuda_runtime.h>
#include <cuda_bf16.h>
#include <cstdint>

#define T 256
#define Bt 64
#define EMB 300
#define HID 256
#define G4 1024
#define NLAB 20

typedef unsigned long long ull;

// ---------------- scratch ----------------
__device__ float g_xproj[2][T][G4][Bt];   // [dir][t][gate][batch]
__device__ float g_h[2][T][HID][Bt];      // [dir][t][hid][batch]
__device__ float g_em[T][Bt][NLAB];
__device__ float g_part[Bt];
__device__ __align__(16) unsigned g_flags[128];
__device__ unsigned g_rel;
__device__ unsigned g_cnt[2][T];          // per-(dir,t) xproj tile counters

// ---------------- f32x2 packed FMA (Blackwell) ----------------
__device__ __forceinline__ ull ffma2(ull a, ull b, ull c) {
    ull d;
    asm("fma.rn.f32x2 %0, %1, %2, %3;" : "=l"(d) : "l"(a), "l"(b), "l"(c));
    return d;
}
__device__ __forceinline__ float lo_hi_sum(ull v) {
    float2 f = *(float2*)&v;
    return f.x + f.y;
}

// ---------------- smem / async helpers ----------------
__device__ __forceinline__ uint32_t smem_u32(const void* p) {
    uint32_t a;
    asm("{ .reg .u64 t; cvta.to.shared.u64 t, %1; cvt.u32.u64 %0, t; }" : "=r"(a) : "l"(p));
    return a;
}
__device__ __forceinline__ void mbar_init(uint32_t mbar, uint32_t cnt) {
    asm volatile("mbarrier.init.shared.b64 [%0], %1;" :: "r"(mbar), "r"(cnt) : "memory");
}
__device__ __forceinline__ void mbar_expect_tx(uint32_t mbar, uint32_t bytes) {
    asm volatile("mbarrier.arrive.expect_tx.shared.b64 _, [%0], %1;" :: "r"(mbar), "r"(bytes) : "memory");
}
__device__ __forceinline__ void mbar_wait(uint32_t mbar, uint32_t phase) {
    asm volatile(
        "{\n\t.reg .pred P;\n"
        "WL_%=:\n\t"
        "mbarrier.try_wait.parity.shared.b64 P, [%0], %1;\n\t"
        "@!P bra WL_%=;\n\t}"
        :: "r"(mbar), "r"(phase) : "memory");
}
__device__ __forceinline__ void bulk_cp(uint32_t dst_smem, const void* src, uint32_t bytes, uint32_t mbar) {
    asm volatile(
        "cp.async.bulk.shared::cluster.global.mbarrier::complete_tx::bytes [%0], [%1], %2, [%3];"
        :: "r"(dst_smem), "l"(src), "r"(bytes), "r"(mbar) : "memory");
}
__device__ __forceinline__ void cp_async16(uint32_t dst, const void* src, uint32_t srcbytes) {
    asm volatile("cp.async.ca.shared.global [%0], [%1], 16, %2;"
                 :: "r"(dst), "l"(src), "r"(srcbytes) : "memory");
}
#define CP_COMMIT() asm volatile("cp.async.commit_group;" ::: "memory")
#define CP_WAIT1()  asm volatile("cp.async.wait_group 1;" ::: "memory")
#define CP_WAIT0()  asm volatile("cp.async.wait_group 0;" ::: "memory")

__device__ __forceinline__ float sigf(float x) { return 1.f / (1.f + __expf(-x)); }

// R13 grid barrier (proven): fence+flag, CTA0-warp0 scalar poll, release word.
__device__ __forceinline__ void grid_barrier2(int bx, int tid, unsigned target)
{
    __threadfence();
    __syncthreads();
    if (tid == 0) ((volatile unsigned*)g_flags)[bx] = target;
    if (bx == 0) {
        if (tid < 32) {
            volatile unsigned* f = g_flags;
            for (;;) {
                bool ok = (f[tid] >= target) & (f[tid + 32] >= target)
                        & (f[tid + 64] >= target) & (f[tid + 96] >= target);
                if (__all_sync(0xffffffffu, ok)) break;
            }
            if (tid == 0) {
                __threadfence();
                *(volatile unsigned*)&g_rel = target;
            }
        }
    } else if (tid == 0) {
        volatile unsigned* r = &g_rel;
        while (*r < target) {}
    }
    __syncthreads();
}

// Fused-kernel dynamic smem:
//  lstm view:   Ws2 [0,32KB) | hs [32KB,96KB) (red overlays hs[0:32KB)) | mbars @96KB
//  worker view: As [0,16KB) | Bs [16KB,32KB) | ws @32KB
#define FUSED_SMEM (98368)

// =============================================================================
// Fused kernel: CTAs 0-127 = persistent BiLSTM (R13), CTAs 128-255 = xproj
// workers (R7 tile pipeline) feeding g_xproj just-in-time via g_cnt.
// =============================================================================
__global__ void __launch_bounds__(256, 2) k_fused(
    const float* __restrict__ emb,
    const float* __restrict__ Wih_f, const float* __restrict__ b_f,
    const float* __restrict__ Wih_b, const float* __restrict__ b_b,
    const float* __restrict__ Whf,   const float* __restrict__ Whb,
    const int*   __restrict__ sent)
{
    extern __shared__ float sm[];
    int bx  = blockIdx.x;
    int tid = threadIdx.x;

    if (bx >= 128) {
        // ===================== xproj worker =====================
        int wk  = bx - 128;          // 0..127
        int dirw = wk >> 6;
        int w6  = wk & 63;
        int grp = w6 >> 4;           // 0..3 : t-phase
        int gbase = (w6 & 15) * 64;  // gate block
        const float* W    = dirw ? Wih_b : Wih_f;
        const float* bias = dirw ? b_b  : b_f;

        float* Asp = sm;             // [2][2048]
        float* Bsp = sm + 4096;      // [2][2048]
        int*   ws  = (int*)(sm + 8192);
        uint32_t as_base = smem_u32(Asp);
        uint32_t bs_base = smem_u32(Bsp);

        int r0 = tid >> 3,          sl0 = tid & 7;
        int r1 = (tid + 256) >> 3,  sl1 = (tid + 256) & 7;
        uint32_t d0 = (uint32_t)(r0 * 128 + ((sl0 ^ (r0 & 7)) << 4));
        uint32_t d1 = (uint32_t)(r1 * 128 + ((sl1 ^ (r1 & 7)) << 4));
        int tx = tid & 15;
        int ty = tid >> 4;
        int sa = tx & 7;
        int sb = ty & 7;

        for (int i = 0; i < 64; i++) {
            int tv = grp + 4 * i;
            int t  = dirw ? (T - 1 - tv) : tv;

            if (tid < 64) ws[tid] = sent[t * 64 + tid];
            __syncthreads();

            const float* arow0 = emb + (size_t)ws[r0] * EMB;
            const float* arow1 = emb + (size_t)ws[r1] * EMB;
            const float* brow0 = W + (size_t)(gbase + r0) * EMB;
            const float* brow1 = W + (size_t)(gbase + r1) * EMB;

            auto issue = [&](int kt, int buf) {
                int k0 = kt * 32;
                uint32_t boff = (uint32_t)(buf * 8192);
                int kg0 = k0 + sl0 * 4, kg1 = k0 + sl1 * 4;
                uint32_t n0b = (kg0 + 4 <= EMB) ? 16u : 0u;
                uint32_t n1b = (kg1 + 4 <= EMB) ? 16u : 0u;
                cp_async16(as_base + boff + d0, arow0 + (n0b ? kg0 : 0), n0b);
                cp_async16(as_base + boff + d1, arow1 + (n1b ? kg1 : 0), n1b);
                cp_async16(bs_base + boff + d0, brow0 + (n0b ? kg0 : 0), n0b);
                cp_async16(bs_base + boff + d1, brow1 + (n1b ? kg1 : 0), n1b);
            };

            ull acc[4][4];
            #pragma unroll
            for (int a = 0; a < 4; a++)
                #pragma unroll
                for (int b = 0; b < 4; b++) acc[a][b] = 0ull;

            issue(0, 0);
            CP_COMMIT();

            for (int kt = 0; kt < 10; kt++) {
                if (kt < 9) {
                    issue(kt + 1, (kt + 1) & 1);
                    CP_COMMIT();
                    CP_WAIT1();
                } else {
                    CP_WAIT0();
                }
                __syncthreads();

                const float* Ab = Asp + (kt & 1) * 2048;
                const float* Bb = Bsp + (kt & 1) * 2048;
                #pragma unroll
                for (int c = 0; c < 8; c++) {
                    ulonglong2 av[4], bv[4];
                    int ca = (c ^ sa) << 2;
                    int cb = (c ^ sb) << 2;
                    #pragma unroll
                    for (int a = 0; a < 4; a++)
                        av[a] = *(const ulonglong2*)&Ab[(tx + 16 * a) * 32 + ca];
                    #pragma unroll
                    for (int b = 0; b < 4; b++)
                        bv[b] = *(const ulonglong2*)&Bb[(ty + 16 * b) * 32 + cb];
                    #pragma unroll
                    for (int a = 0; a < 4; a++)
                        #pragma unroll
                        for (int b = 0; b < 4; b++) {
                            acc[a][b] = ffma2(av[a].x, bv[b].x, acc[a][b]);
                            acc[a][b] = ffma2(av[a].y, bv[b].y, acc[a][b]);
                        }
                }
                __syncthreads();
            }

            #pragma unroll
            for (int b = 0; b < 4; b++) {
                int g = gbase + ty + 16 * b;
                float bv = bias[g];
                #pragma unroll
                for (int a = 0; a < 4; a++) {
                    int m = tx + 16 * a;
                    g_xproj[dirw][t][g][m] = lo_hi_sum(acc[a][b]) + bv;
                }
            }
            __syncthreads();                 // all stores issued, smem reads done
            if (tid == 0) {
                __threadfence();             // tile stores -> GPU scope
                atomicAdd(&g_cnt[dirw][t], 1u);
            }
            __syncthreads();                 // before ws rewrite next tile
        }
        return;
    }

    // ===================== lstm CTA (R13 + red/hs overlay + cnt gate) ========
    ull*   Ws2 = (ull*)sm;                    // [k=256][16] dup pairs, 32KB
    float* hs  = sm + 8192;                   // [256][64], 64KB
    float* red = hs;                          // overlay: first 32KB of hs
    uint32_t mbar0 = smem_u32(sm + 24576);    // 4 mbarriers @96KB

    int dir = bx >> 6;
    int cc  = bx & 63;
    const float* Whh = dir ? Whb : Whf;

    unsigned base0 = ((volatile unsigned*)g_flags)[bx];

    for (int idx = tid; idx < 4096; idx += 256) {
        int k = idx & 255, r = idx >> 8;
        int q = r >> 2, j = r & 3;
        float w = Whh[(q * 256 + 4 * cc + j) * HID + k];
        float2 w2 = make_float2(w, w);
        Ws2[k * 16 + r] = *(ull*)&w2;
    }
    if (tid == 0)
        for (int ch = 0; ch < 4; ch++) mbar_init(mbar0 + ch * 8, 1);
    __syncthreads();

    int lane = tid & 31;
    int ks   = tid >> 5;
    int gq   = lane >> 3;
    int bq   = lane & 7;
    int kbase = ks * 32;
    uint32_t my_mbar = mbar0 + (ks >> 1) * 8;

    int jrow = tid >> 6;
    int bcol = tid & 63;
    float cstate = 0.f;

    float* hb = &g_h[dir][0][0][0];
    uint32_t hs_smem = smem_u32(hs);

    for (int step = 0; step < T; step++) {
        int t = dir ? (T - 1 - step) : step;

        if (tid == 0) {
            if (step > 0) {
                int tprev = dir ? (t + 1) : (t - 1);
                const float* src = hb + tprev * HID * Bt;
                #pragma unroll
                for (int ch = 0; ch < 4; ch++) {
                    mbar_expect_tx(mbar0 + ch * 8, 16384);
                    bulk_cp(hs_smem + ch * 16384, src + ch * 4096, 16384, mbar0 + ch * 8);
                }
            }
            // gate on xproj availability for this t (workers usually ahead)
            volatile unsigned* cp = &g_cnt[dir][t];
            while (*cp < 16u) {}
        }
        __syncthreads();   // (A) xproj[dir][t] ready for all threads

        float xp[4];
        #pragma unroll
        for (int q2 = 0; q2 < 4; q2++)
            xp[q2] = g_xproj[dir][t][q2 * 256 + 4 * cc + jrow][bcol];

        ull acc[4][4];
        #pragma unroll
        for (int j = 0; j < 4; j++)
            #pragma unroll
            for (int p = 0; p < 4; p++) acc[j][p] = 0ull;

        if (step > 0) {
            mbar_wait(my_mbar, (unsigned)(step - 1) & 1u);
            #pragma unroll 8
            for (int kk = 0; kk < 32; kk++) {
                int k = kbase + kk;
                const ull* wrow = Ws2 + k * 16 + gq * 4;
                ulonglong2 wv0 = *(const ulonglong2*)wrow;
                ulonglong2 wv1 = *(const ulonglong2*)(wrow + 2);
                const float* hrow = hs + k * 64 + bq * 8;
                ulonglong2 ha  = *(const ulonglong2*)hrow;
                ulonglong2 hb2 = *(const ulonglong2*)(hrow + 4);
                acc[0][0] = ffma2(wv0.x, ha.x,  acc[0][0]);
                acc[0][1] = ffma2(wv0.x, ha.y,  acc[0][1]);
                acc[0][2] = ffma2(wv0.x, hb2.x, acc[0][2]);
                acc[0][3] = ffma2(wv0.x, hb2.y, acc[0][3]);
                acc[1][0] = ffma2(wv0.y, ha.x,  acc[1][0]);
                acc[1][1] = ffma2(wv0.y, ha.y,  acc[1][1]);
                acc[1][2] = ffma2(wv0.y, hb2.x, acc[1][2]);
                acc[1][3] = ffma2(wv0.y, hb2.y, acc[1][3]);
                acc[2][0] = ffma2(wv1.x, ha.x,  acc[2][0]);
                acc[2][1] = ffma2(wv1.x, ha.y,  acc[2][1]);
                acc[2][2] = ffma2(wv1.x, hb2.x, acc[2][2]);
                acc[2][3] = ffma2(wv1.x, hb2.y, acc[2][3]);
                acc[3][0] = ffma2(wv1.y, ha.x,  acc[3][0]);
                acc[3][1] = ffma2(wv1.y, ha.y,  acc[3][1]);
                acc[3][2] = ffma2(wv1.y, hb2.x, acc[3][2]);
                acc[3][3] = ffma2(wv1.y, hb2.y, acc[3][3]);
            }
        }

        __syncthreads();   // (B) all hs reads done before red overlay stores

        {
            float* rrow = red + (ks * 16 + gq * 4) * 64 + bq * 8;
            #pragma unroll
            for (int j = 0; j < 4; j++) {
                ulonglong2 v0; v0.x = acc[j][0]; v0.y = acc[j][1];
                ulonglong2 v1; v1.x = acc[j][2]; v1.y = acc[j][3];
                *(ulonglong2*)(rrow + j * 64)     = v0;
                *(ulonglong2*)(rrow + j * 64 + 4) = v1;
            }
        }
        __syncthreads();   // (C)

        float iv = xp[0], fv = xp[1], gv = xp[2], ov = xp[3];
        #pragma unroll
        for (int s = 0; s < 8; s++) {
            iv += red[(s * 16 +  0 + jrow) * 64 + bcol];
            fv += red[(s * 16 +  4 + jrow) * 64 + bcol];
            gv += red[(s * 16 +  8 + jrow) * 64 + bcol];
            ov += red[(s * 16 + 12 + jrow) * 64 + bcol];
        }
        cstate = sigf(fv) * cstate + sigf(iv) * tanhf(gv);
        float hv = sigf(ov) * tanhf(cstate);
        hb[t * HID * Bt + (4 * cc + jrow) * Bt + bcol] = hv;

        grid_barrier2(bx, tid, base0 + (unsigned)(step + 1));
    }
}

// =============================================================================
// Kernel 3: emissions
// =============================================================================
__global__ void __launch_bounds__(256) k_emis(
    const float* __restrict__ Wt, const float* __restrict__ bt)
{
    extern __shared__ float sm[];
    float* Wts = sm;
    float* hch = sm + 10240;

    int t = blockIdx.x, tid = threadIdx.x;
    for (int i = tid; i < NLAB * 2 * HID; i += 256) Wts[i] = Wt[i];

    float acc[5] = {0.f, 0.f, 0.f, 0.f, 0.f};
    int b = tid & 63;
    int lbase = tid >> 6;

    for (int d = 0; d < 2; d++) {
        const float* hsrc = &g_h[d][t][0][0];
        for (int jc = 0; jc < 4; jc++) {
            __syncthreads();
            for (int i = tid; i < 4096; i += 256) hch[i] = hsrc[jc * 4096 + i];
            __syncthreads();
            #pragma unroll 4
            for (int j2 = 0; j2 < 64; j2++) {
                float hv = hch[j2 * 64 + b];
                #pragma unroll
                for (int s = 0; s < 5; s++) {
                    int l = lbase + 4 * s;
                    acc[s] += hv * Wts[l * 2 * HID + d * HID + jc * 64 + j2];
                }
            }
        }
    }
    #pragma unroll
    for (int s = 0; s < 5; s++) {
        int l = lbase + 4 * s;
        g_em[t][b][l] = acc[s] + bt[l];
    }
}

// =============================================================================
// Kernel 4: CRF per batch
// =============================================================================
__global__ void __launch_bounds__(64) k_crf(
    const int* __restrict__ sent, const int* __restrict__ labels,
    const float* __restrict__ start_t, const float* __restrict__ end_t,
    const float* __restrict__ trans)
{
    int b = blockIdx.x;
    int tid = threadIdx.x;
    __shared__ float s_score, s_denom;

    if (tid < 32) {
        int j = tid;
        float tcol[NLAB];
        #pragma unroll
        for (int i = 0; i < NLAB; i++) tcol[i] = (j < NLAB) ? trans[i * NLAB + j] : 0.f;
        float alpha = (j < NLAB) ? (start_t[j] + g_em[0][b][j]) : -1e30f;

        for (int t = 1; t < T; t++) {
            bool m = (sent[t * 64 + b] != 0);
            float em = (j < NLAB) ? g_em[t][b][j] : 0.f;
            float s[NLAB], mx = -1e30f;
            #pragma unroll
            for (int i = 0; i < NLAB; i++) {
                float ai = __shfl_sync(0xffffffffu, alpha, i);
                s[i] = ai + tcol[i];
                mx = fmaxf(mx, s[i]);
            }
            float sum = 0.f;
            #pragma unroll
            for (int i = 0; i < NLAB; i++) sum += __expf(s[i] - mx);
            float nxt = em + mx + __logf(sum);
            if (j < NLAB && m) alpha = nxt;
        }
        float v = (j < NLAB) ? (alpha + end_t[j]) : -1e30f;
        float mx = v;
        #pragma unroll
        for (int o = 16; o > 0; o >>= 1) mx = fmaxf(mx, __shfl_xor_sync(0xffffffffu, mx, o));
        float e = (j < NLAB) ? __expf(v - mx) : 0.f;
        #pragma unroll
        for (int o = 16; o > 0; o >>= 1) e += __shfl_xor_sync(0xffffffffu, e, o);
        if (tid == 0) s_denom = mx + __logf(e);
    } else {
        int l = tid - 32;
        float part = 0.f; int cnt = 0;
        for (int t = l; t < T; t += 32) {
            bool m = (sent[t * 64 + b] != 0);
            cnt += m ? 1 : 0;
            if (t >= 1 && m) {
                int tp = labels[(t - 1) * 64 + b];
                int tc = labels[t * 64 + b];
                part += trans[tp * NLAB + tc] + g_em[t][b][tc];
            }
        }
        #pragma unroll
        for (int o = 16; o > 0; o >>= 1) {
            part += __shfl_xor_sync(0xffffffffu, part, o);
            cnt  += __shfl_xor_sync(0xffffffffu, cnt, o);
        }
        if (l == 0) {
            int tag0 = labels[b];
            float score = start_t[tag0] + g_em[0][b][tag0] + part;
            int se = cnt - 1;
            int last = labels[se * 64 + b];
            score += end_t[last];
            s_score = score;
        }
    }
    __syncthreads();
    if (tid == 0) g_part[b] = s_denom - s_score;
}

__global__ void k_reduce(float* out)
{
    if (threadIdx.x == 0) {
        float s = 0.f;
        for (int b = 0; b < Bt; b++) s += g_part[b];
        out[0] = s;
    }
}

__global__ void k_reset()
{
    int i = threadIdx.x;
    if (i < 128) g_flags[i] = 0u;
    if (i == 0)  g_rel = 0u;
    unsigned* c = &g_cnt[0][0];
    for (int k = i; k < 2 * T; k += 512) c[k] = 0u;
}

// =============================================================================
extern "C" void kernel_launch(void* const* d_in, const int* in_sizes, int n_in,
                              void* d_out, int out_size)
{
    const float* emb    = (const float*)d_in[0];
    const float* Wih_f  = (const float*)d_in[1];
    const float* Whh_f  = (const float*)d_in[2];
    const float* b_f    = (const float*)d_in[3];
    const float* Wih_b  = (const float*)d_in[4];
    const float* Whh_b  = (const float*)d_in[5];
    const float* b_b    = (const float*)d_in[6];
    const float* W_top  = (const float*)d_in[7];
    const float* b_top  = (const float*)d_in[8];
    const float* startt = (const float*)d_in[9];
    const float* endt   = (const float*)d_in[10];
    const float* trans  = (const float*)d_in[11];
    const int*   sent   = (const int*)d_in[12];
    const int*   labels = (const int*)d_in[13];
    float* out = (float*)d_out;

    cudaFuncSetAttribute(k_fused, cudaFuncAttributeMaxDynamicSharedMemorySize, FUSED_SMEM);
    cudaFuncSetAttribute(k_emis,  cudaFuncAttributeMaxDynamicSharedMemorySize, 57344);

    k_reset<<<1, 512>>>();
    k_fused<<<256, 256, FUSED_SMEM>>>(emb, Wih_f, b_f, Wih_b, b_b,
                                      Whh_f, Whh_b, sent);
    k_emis <<<256, 256, 57344>>>(W_top, b_top);
    k_crf  <<<64, 64>>>(sent, labels, startt, endt, trans);
    k_reduce<<<1, 32>>>(out);
}